// round 2
// baseline (speedup 1.0000x reference)
#include <cuda_runtime.h>
#include <cuda_bf16.h>

// Focal loss (2-class) full reduction:
//   t   = (gold >= 0.5)
//   oh1 = t * 0.25 ; oh0 = (1 - oh1) * 0.75
//   lp  = log_softmax(pred) ; p = softmax(pred)
//   loss_row = -(oh0*lp0*(1-p0)^2 + oh1*lp1*(1-p1)^2)
//   out = sum(loss_row)            (CORR = 1)
// With 2 classes: 1-p0 = p1, 1-p1 = p0.

__global__ void zero_out_kernel(float* out) {
    out[0] = 0.0f;
}

__device__ __forceinline__ float focal_row(float x0, float x1, float g) {
    float t   = (g >= 0.5f) ? 1.0f : 0.0f;
    float oh1 = t * 0.25f;
    float oh0 = (1.0f - oh1) * 0.75f;

    float m  = fmaxf(x0, x1);
    float e0 = __expf(x0 - m);
    float e1 = __expf(x1 - m);
    float s  = e0 + e1;
    float inv = __frcp_rn(s);
    float p0 = e0 * inv;
    float p1 = e1 * inv;
    float ls = __logf(s);
    float lp0 = (x0 - m) - ls;
    float lp1 = (x1 - m) - ls;

    // focal0 = (1-p0)^2 = p1^2 ; focal1 = (1-p1)^2 = p0^2
    return -(oh0 * lp0 * (p1 * p1) + oh1 * lp1 * (p0 * p0));
}

__global__ void __launch_bounds__(256)
focal_loss_kernel(const float* __restrict__ pred,   // [N, 2] f32
                  const float* __restrict__ gold,   // [N]    f32
                  float* __restrict__ out,
                  int n)                            // N rows
{
    const float4* __restrict__ pred4 = (const float4*)pred;  // N/2 float4
    const float4* __restrict__ gold4 = (const float4*)gold;  // N/4 float4

    float acc = 0.0f;

    int n4 = n >> 2;
    int stride = gridDim.x * blockDim.x;
    int tid = blockIdx.x * blockDim.x + threadIdx.x;

    for (int i = tid; i < n4; i += stride) {
        // 4 rows per iteration: two float4 of pred (interleaved x0,x1), one float4 of gold
        float4 pa = pred4[2 * i];
        float4 pb = pred4[2 * i + 1];
        float4 g  = gold4[i];

        acc += focal_row(pa.x, pa.y, g.x);
        acc += focal_row(pa.z, pa.w, g.y);
        acc += focal_row(pb.x, pb.y, g.z);
        acc += focal_row(pb.z, pb.w, g.w);
    }

    // Scalar tail for n % 4 rows (no-op when N divisible by 4)
    int tail_start = n4 << 2;
    for (int r = tail_start + tid; r < n; r += stride) {
        acc += focal_row(pred[2 * r], pred[2 * r + 1], gold[r]);
    }

    // Warp reduction
    #pragma unroll
    for (int off = 16; off > 0; off >>= 1)
        acc += __shfl_xor_sync(0xFFFFFFFFu, acc, off);

    // Block reduction via shared
    __shared__ float warp_sums[8];  // 256 threads -> 8 warps
    int lane = threadIdx.x & 31;
    int wid  = threadIdx.x >> 5;
    if (lane == 0) warp_sums[wid] = acc;
    __syncthreads();

    if (wid == 0) {
        float v = (lane < 8) ? warp_sums[lane] : 0.0f;
        #pragma unroll
        for (int off = 4; off > 0; off >>= 1)
            v += __shfl_xor_sync(0xFFFFFFFFu, v, off);
        if (lane == 0)
            atomicAdd(out, v);
    }
}

extern "C" void kernel_launch(void* const* d_in, const int* in_sizes, int n_in,
                              void* d_out, int out_size) {
    // Auto-detect input order by size: pred has 2*N elements, gold has N.
    const float* pred;
    const float* gold;
    int n;
    if (n_in >= 2 && in_sizes[0] >= in_sizes[1]) {
        pred = (const float*)d_in[0];
        gold = (const float*)d_in[1];
        n = in_sizes[1];
    } else {
        pred = (const float*)d_in[1];
        gold = (const float*)d_in[0];
        n = in_sizes[0];
    }
    float* out = (float*)d_out;

    zero_out_kernel<<<1, 1>>>(out);

    const int threads = 256;
    const int blocks  = 2368;   // grid-stride; ~7 iterations/thread at N=2^24
    focal_loss_kernel<<<blocks, threads>>>(pred, gold, out, n);
}

// round 3
// speedup vs baseline: 1.0017x; 1.0017x over previous
#include <cuda_runtime.h>
#include <cuda_bf16.h>

// Focal loss (2-class) full reduction via sigmoid reformulation:
//   d = x1 - x0, a = -|d|, e = exp(a), s = 1 + e
//   p_max = 1/s, p_min = e/s, lp_max = -log(s), lp_min = a - log(s)
//   loss = -(A*lp_max*p_min^2 + B*lp_min*p_max^2),
//   (A,B) = (oh1,oh0) if x1>=x0 else (oh0,oh1)
//   oh1 = (g>=0.5) ? 0.25 : 0 ; oh0 = (g>=0.5) ? 0.5625 : 0.75
//   out = sum over rows

__global__ void zero_out_kernel(float* out) {
    out[0] = 0.0f;
}

__device__ __forceinline__ float rcp_approx(float x) {
    float r;
    asm("rcp.approx.f32 %0, %1;" : "=f"(r) : "f"(x));
    return r;
}

__device__ __forceinline__ float focal_row(float x0, float x1, float g) {
    float d  = x1 - x0;
    float a  = -fabsf(d);          // <= 0
    float e  = __expf(a);          // exp(-|d|) in (0,1] : 1 EX2
    float s  = 1.0f + e;
    float r  = rcp_approx(s);      // 1 MUFU.RCP (approx)
    float ls = __logf(s);          // 1 LG2 ; log(s) = softplus(-|d|)

    float pmax  = r;
    float pmin  = e * r;
    float lpmin = a - ls;          // lpmax = -ls (sign folded below)

    bool posd = d >= 0.0f;
    bool posg = g >= 0.5f;
    float oh1 = posg ? 0.25f   : 0.0f;
    float oh0 = posg ? 0.5625f : 0.75f;
    float A = posd ? oh1 : oh0;    // coefficient of max-logit class
    float B = posd ? oh0 : oh1;    // coefficient of min-logit class

    // loss = -(A * (-ls) * pmin^2 + B * lpmin * pmax^2)
    //      = A*ls*pmin^2 - B*lpmin*pmax^2
    float t0 = A * ls;
    float t1 = B * lpmin;
    return fmaf(t0, pmin * pmin, -(t1 * (pmax * pmax)));
}

__global__ void __launch_bounds__(256)
focal_loss_kernel(const float* __restrict__ pred,   // [N, 2] f32
                  const float* __restrict__ gold,   // [N]    f32
                  float* __restrict__ out,
                  int n)                            // N rows
{
    const float4* __restrict__ pred4 = (const float4*)pred;  // N/2 float4
    const float4* __restrict__ gold4 = (const float4*)gold;  // N/4 float4

    float acc = 0.0f;

    int n8 = n >> 3;                       // iterations of 8 rows
    int stride = gridDim.x * blockDim.x;
    int tid = blockIdx.x * blockDim.x + threadIdx.x;

    for (int i = tid; i < n8; i += stride) {
        // 8 rows per iteration: 4 float4 of pred + 2 float4 of gold (6 LDG.128)
        float4 pa = pred4[4 * i];
        float4 pb = pred4[4 * i + 1];
        float4 pc = pred4[4 * i + 2];
        float4 pd = pred4[4 * i + 3];
        float4 ga = gold4[2 * i];
        float4 gb = gold4[2 * i + 1];

        acc += focal_row(pa.x, pa.y, ga.x);
        acc += focal_row(pa.z, pa.w, ga.y);
        acc += focal_row(pb.x, pb.y, ga.z);
        acc += focal_row(pb.z, pb.w, ga.w);
        acc += focal_row(pc.x, pc.y, gb.x);
        acc += focal_row(pc.z, pc.w, gb.y);
        acc += focal_row(pd.x, pd.y, gb.z);
        acc += focal_row(pd.z, pd.w, gb.w);
    }

    // Scalar tail for n % 8 rows (no-op when N divisible by 8)
    int tail_start = n8 << 3;
    for (int r = tail_start + tid; r < n; r += stride) {
        acc += focal_row(pred[2 * r], pred[2 * r + 1], gold[r]);
    }

    // Warp reduction
    #pragma unroll
    for (int off = 16; off > 0; off >>= 1)
        acc += __shfl_xor_sync(0xFFFFFFFFu, acc, off);

    // Block reduction via shared
    __shared__ float warp_sums[8];  // 256 threads -> 8 warps
    int lane = threadIdx.x & 31;
    int wid  = threadIdx.x >> 5;
    if (lane == 0) warp_sums[wid] = acc;
    __syncthreads();

    if (wid == 0) {
        float v = (lane < 8) ? warp_sums[lane] : 0.0f;
        #pragma unroll
        for (int off = 4; off > 0; off >>= 1)
            v += __shfl_xor_sync(0xFFFFFFFFu, v, off);
        if (lane == 0)
            atomicAdd(out, v);
    }
}

extern "C" void kernel_launch(void* const* d_in, const int* in_sizes, int n_in,
                              void* d_out, int out_size) {
    // Auto-detect input order by size: pred has 2*N elements, gold has N.
    const float* pred;
    const float* gold;
    int n;
    if (n_in >= 2 && in_sizes[0] >= in_sizes[1]) {
        pred = (const float*)d_in[0];
        gold = (const float*)d_in[1];
        n = in_sizes[1];
    } else {
        pred = (const float*)d_in[1];
        gold = (const float*)d_in[0];
        n = in_sizes[0];
    }
    float* out = (float*)d_out;

    zero_out_kernel<<<1, 1>>>(out);

    const int threads = 256;
    const int blocks  = 2048;   // 524288 threads: exactly 4 iters/thread at N=2^24
    focal_loss_kernel<<<blocks, threads>>>(pred, gold, out, n);
}